// round 7
// baseline (speedup 1.0000x reference)
#include <cuda_runtime.h>
#include <cuda_bf16.h>
#include <cstdint>
#include <cstddef>

#define NN 50000
#define NE 1600000
#define DD 128
#define RR 24
#define BB 8
#define KTOT (BB*DD + DD)     /* 1152 */
#define NR (NN*RR)            /* 1,200,000 */

// ---------------- device scratch (no allocations allowed) ----------------
__device__ float g_h0[(size_t)NN * DD];
__device__ float g_h1[(size_t)NN * DD];
__device__ float g_A [(size_t)NN * KTOT];
__device__ float g_Wc[(size_t)KTOT * DD];
__device__ int   g_cnt[NR];
__device__ int   g_seg_off[NR];     // per-segment start (becomes END after k_place)
__device__ int   g_sorted_src[NE];  // src ids grouped by (dst*R + type) segment
__device__ int   g_cursor;          // global allocation cursor for segments

// round-to-nearest tf32
__device__ __forceinline__ float tf32r(float x) {
    uint32_t u;
    asm("cvt.rna.tf32.f32 %0, %1;" : "=r"(u) : "f"(x));
    return __uint_as_float(u);
}

__device__ __forceinline__ void cp16(void* smem_ptr, const void* gptr, bool pred) {
    uint32_t s = (uint32_t)__cvta_generic_to_shared(smem_ptr);
    int sz = pred ? 16 : 0;
    asm volatile("cp.async.cg.shared.global [%0], [%1], 16, %2;\n"
                 :: "r"(s), "l"(gptr), "r"(sz));
}

// ---------------- setup kernels ----------------

__global__ void k_embed(const int* __restrict__ x, const float4* __restrict__ emb) {
    int idx = blockIdx.x * blockDim.x + threadIdx.x;
    if (idx >= NN * 32) return;
    int n = idx >> 5;
    int c = idx & 31;
    ((float4*)g_h0)[idx] = emb[(size_t)x[n] * 32 + c];
}

__global__ void k_zero_cnt() {   // NR = 1.2M ints = 300K int4
    int i = blockIdx.x * blockDim.x + threadIdx.x;
    if (i == 0) g_cursor = 0;
    if (i < NR / 4) ((int4*)g_cnt)[i] = make_int4(0, 0, 0, 0);
}

__global__ void k_hist(const int* __restrict__ dst, const int* __restrict__ ety) {
    int e = blockIdx.x * blockDim.x + threadIdx.x;
    if (e < NE) atomicAdd(&g_cnt[dst[e] * RR + ety[e]], 1);
}

// Parallel segment-offset assignment: block-local exclusive scan of 256 counts,
// one global atomicAdd per block. Segment order is arbitrary; only intra-segment
// contiguity matters downstream.
__global__ __launch_bounds__(256) void k_seg_assign() {
    __shared__ int wtot[8];
    __shared__ int s_base;
    int i = blockIdx.x * 256 + threadIdx.x;
    int lane = threadIdx.x & 31, wid = threadIdx.x >> 5;
    int c = (i < NR) ? g_cnt[i] : 0;
    int incl = c;
    #pragma unroll
    for (int d = 1; d < 32; d <<= 1) {
        int t = __shfl_up_sync(0xffffffffu, incl, d);
        if (lane >= d) incl += t;
    }
    if (lane == 31) wtot[wid] = incl;
    __syncthreads();
    if (threadIdx.x == 0) {
        int s = 0;
        #pragma unroll
        for (int j = 0; j < 8; j++) { int t = wtot[j]; wtot[j] = s; s += t; }
        s_base = atomicAdd(&g_cursor, s);
    }
    __syncthreads();
    if (i < NR) g_seg_off[i] = s_base + wtot[wid] + incl - c;
}

__global__ void k_place(const int* __restrict__ src, const int* __restrict__ dst,
                        const int* __restrict__ ety) {
    int e = blockIdx.x * blockDim.x + threadIdx.x;
    if (e >= NE) return;
    int pos = atomicAdd(&g_seg_off[dst[e] * RR + ety[e]], 1);   // seg_off becomes END
    g_sorted_src[pos] = src[e];
}

__global__ void k_wc(const float4* __restrict__ bases, const float4* __restrict__ root) {
    int i = blockIdx.x * blockDim.x + threadIdx.x;           // over KTOT*DD/4 float4
    if (i >= KTOT * DD / 4) return;
    float4 v = (i < BB * DD * DD / 4) ? bases[i] : root[i - BB * DD * DD / 4];
    v.x = tf32r(v.x); v.y = tf32r(v.y); v.z = tf32r(v.z); v.w = tf32r(v.w);
    ((float4*)g_Wc)[i] = v;
}

// ---------------- aggregation: one warp per node, float4 lanes ----------------
__global__ __launch_bounds__(256) void k_aggregate(int use_h1, const float* __restrict__ comp) {
    const float4* __restrict__ h4 = (const float4*)(use_h1 ? g_h1 : g_h0);
    const int* __restrict__ srt = g_sorted_src;

    __shared__ float s_comp[RR * BB];
    for (int j = threadIdx.x; j < RR * BB; j += 256) s_comp[j] = comp[j];
    __syncthreads();

    const int lane = threadIdx.x & 31;
    const int n = (blockIdx.x * 256 + threadIdx.x) >> 5;   // 6250 blocks * 8 warps = NN exactly

    int end_l = 0, cnt_l = 0;
    if (lane < RR) {
        end_l = g_seg_off[n * RR + lane];
        cnt_l = g_cnt[n * RR + lane];
    }

    float z[BB][4];
    #pragma unroll
    for (int b = 0; b < BB; b++)
        #pragma unroll
        for (int j = 0; j < 4; j++) z[b][j] = 0.f;

    for (int r = 0; r < RR; r++) {
        int c = __shfl_sync(0xffffffffu, cnt_l, r);
        if (c == 0) continue;
        int e1 = __shfl_sync(0xffffffffu, end_l, r);
        int e0 = e1 - c;

        float4 a0 = make_float4(0.f, 0.f, 0.f, 0.f);
        float4 a1 = a0, a2 = a0, a3 = a0;
        int e = e0;
        for (; e + 3 < e1; e += 4) {
            int s0 = __ldg(&srt[e]);
            int s1 = __ldg(&srt[e + 1]);
            int s2 = __ldg(&srt[e + 2]);
            int s3 = __ldg(&srt[e + 3]);
            float4 v0 = __ldg(&h4[s0 * 32 + lane]);
            float4 v1 = __ldg(&h4[s1 * 32 + lane]);
            float4 v2 = __ldg(&h4[s2 * 32 + lane]);
            float4 v3 = __ldg(&h4[s3 * 32 + lane]);
            a0.x += v0.x; a0.y += v0.y; a0.z += v0.z; a0.w += v0.w;
            a1.x += v1.x; a1.y += v1.y; a1.z += v1.z; a1.w += v1.w;
            a2.x += v2.x; a2.y += v2.y; a2.z += v2.z; a2.w += v2.w;
            a3.x += v3.x; a3.y += v3.y; a3.z += v3.z; a3.w += v3.w;
        }
        for (; e < e1; e++) {
            int s0 = __ldg(&srt[e]);
            float4 v0 = __ldg(&h4[s0 * 32 + lane]);
            a0.x += v0.x; a0.y += v0.y; a0.z += v0.z; a0.w += v0.w;
        }
        float inv = 1.0f / (float)c;
        float m0 = ((a0.x + a1.x) + (a2.x + a3.x)) * inv;
        float m1 = ((a0.y + a1.y) + (a2.y + a3.y)) * inv;
        float m2 = ((a0.z + a1.z) + (a2.z + a3.z)) * inv;
        float m3 = ((a0.w + a1.w) + (a2.w + a3.w)) * inv;
        #pragma unroll
        for (int b = 0; b < BB; b++) {
            float w = s_comp[r * BB + b];
            z[b][0] = fmaf(w, m0, z[b][0]);
            z[b][1] = fmaf(w, m1, z[b][1]);
            z[b][2] = fmaf(w, m2, z[b][2]);
            z[b][3] = fmaf(w, m3, z[b][3]);
        }
    }

    float4* Arow = (float4*)&g_A[(size_t)n * KTOT];
    #pragma unroll
    for (int b = 0; b < BB; b++) {
        float4 v;
        v.x = tf32r(z[b][0]); v.y = tf32r(z[b][1]);
        v.z = tf32r(z[b][2]); v.w = tf32r(z[b][3]);
        Arow[b * 32 + lane] = v;
    }
    float4 hv = __ldg(&h4[n * 32 + lane]);
    hv.x = tf32r(hv.x); hv.y = tf32r(hv.y); hv.z = tf32r(hv.z); hv.w = tf32r(hv.w);
    Arow[BB * 32 + lane] = hv;
}

// ---------------- tf32 tensor-core GEMM ----------------
// out[N,128] = g_A[N,1152] @ g_Wc[1152,128] + bias (optional relu)
// BM=128, BN=128, BK=16, 256 threads (8 warps, warp tile 32x64), 2-stage cp.async.
// Static smem = 37.9 KB (< 48 KB static cap), 2 blocks/SM.
#define GBM 128
#define GBK 16
#define NITER (KTOT / GBK)   /* 72 */

__global__ __launch_bounds__(256, 2) void k_gemm_tc(const float* __restrict__ bias,
                                                    float* __restrict__ outp, int relu) {
    __shared__ float As[2][GBM][20];    // [m][k], stride 20 -> conflict-free frags
    __shared__ float Bs[2][GBK][136];   // [k][n], stride 136 -> conflict-free frags

    const int tid  = threadIdx.x;
    const int wid  = tid >> 5;
    const int lane = tid & 31;
    const int g    = lane >> 2;
    const int q    = lane & 3;
    const int warp_m = (wid >> 1) * 32;   // 0,32,64,96
    const int warp_n = (wid & 1) * 64;    // 0,64
    const int row0 = blockIdx.x * GBM;

    float acc[2][8][4];
    #pragma unroll
    for (int mi = 0; mi < 2; mi++)
        #pragma unroll
        for (int nj = 0; nj < 8; nj++)
            #pragma unroll
            for (int k = 0; k < 4; k++) acc[mi][nj][k] = 0.f;

    // A tile: 128x16 floats = 512 float4; 2 per thread
    // B tile: 16x128 floats = 512 float4; 2 per thread
    #define LOAD_TILES(K0, BUF)                                                   \
    do {                                                                          \
        _Pragma("unroll")                                                         \
        for (int j = 0; j < 2; j++) {                                             \
            int idx = tid + j * 256;                                              \
            int ar = idx >> 2, ac = (idx & 3) * 4;                                \
            bool ok = (row0 + ar) < NN;                                           \
            const float* src = ok ? &g_A[(size_t)(row0 + ar) * KTOT + (K0) + ac]  \
                                  : &g_A[0];                                      \
            cp16(&As[BUF][ar][ac], src, ok);                                      \
        }                                                                         \
        _Pragma("unroll")                                                         \
        for (int j = 0; j < 2; j++) {                                             \
            int idx = tid + j * 256;                                              \
            int br = idx >> 5, bc = (idx & 31) * 4;                               \
            cp16(&Bs[BUF][br][bc], &g_Wc[(size_t)((K0) + br) * DD + bc], true);   \
        }                                                                         \
    } while (0)

    LOAD_TILES(0, 0);
    asm volatile("cp.async.commit_group;");

    for (int it = 0; it < NITER; it++) {
        const int cur = it & 1;
        const int nxt = cur ^ 1;
        if (it + 1 < NITER) LOAD_TILES((it + 1) * GBK, nxt);
        asm volatile("cp.async.commit_group;");
        asm volatile("cp.async.wait_group 1;");
        __syncthreads();

        #pragma unroll
        for (int s = 0; s < 2; s++) {
            const int kb = s * 8;
            uint32_t af[2][4];
            uint32_t bf[8][2];
            #pragma unroll
            for (int mi = 0; mi < 2; mi++) {
                int m = warp_m + mi * 16 + g;
                af[mi][0] = __float_as_uint(As[cur][m][kb + q]);
                af[mi][1] = __float_as_uint(As[cur][m + 8][kb + q]);
                af[mi][2] = __float_as_uint(As[cur][m][kb + q + 4]);
                af[mi][3] = __float_as_uint(As[cur][m + 8][kb + q + 4]);
            }
            #pragma unroll
            for (int nj = 0; nj < 8; nj++) {
                int n = warp_n + nj * 8 + g;
                bf[nj][0] = __float_as_uint(Bs[cur][kb + q][n]);
                bf[nj][1] = __float_as_uint(Bs[cur][kb + q + 4][n]);
            }
            #pragma unroll
            for (int mi = 0; mi < 2; mi++)
                #pragma unroll
                for (int nj = 0; nj < 8; nj++) {
                    asm volatile(
                        "mma.sync.aligned.m16n8k8.row.col.f32.tf32.tf32.f32 "
                        "{%0,%1,%2,%3}, {%4,%5,%6,%7}, {%8,%9}, {%0,%1,%2,%3};\n"
                        : "+f"(acc[mi][nj][0]), "+f"(acc[mi][nj][1]),
                          "+f"(acc[mi][nj][2]), "+f"(acc[mi][nj][3])
                        : "r"(af[mi][0]), "r"(af[mi][1]), "r"(af[mi][2]), "r"(af[mi][3]),
                          "r"(bf[nj][0]), "r"(bf[nj][1]));
                }
        }
        __syncthreads();
    }

    float* dstb = outp ? outp : g_h1;
    #pragma unroll
    for (int mi = 0; mi < 2; mi++) {
        #pragma unroll
        for (int nj = 0; nj < 8; nj++) {
            int c  = warp_n + nj * 8 + q * 2;
            float b0 = __ldg(&bias[c]);
            float b1 = __ldg(&bias[c + 1]);
            int ra = row0 + warp_m + mi * 16 + g;
            int rb = ra + 8;
            float2 v0, v1;
            v0.x = acc[mi][nj][0] + b0; v0.y = acc[mi][nj][1] + b1;
            v1.x = acc[mi][nj][2] + b0; v1.y = acc[mi][nj][3] + b1;
            if (relu) {
                v0.x = fmaxf(v0.x, 0.f); v0.y = fmaxf(v0.y, 0.f);
                v1.x = fmaxf(v1.x, 0.f); v1.y = fmaxf(v1.y, 0.f);
            }
            if (ra < NN) *(float2*)&dstb[(size_t)ra * DD + c] = v0;
            if (rb < NN) *(float2*)&dstb[(size_t)rb * DD + c] = v1;
        }
    }
}

// ---------------- host launch ----------------
extern "C" void kernel_launch(void* const* d_in, const int* in_sizes, int n_in,
                              void* d_out, int out_size) {
    const int*   x      = (const int*)  d_in[0];
    const int*   ei     = (const int*)  d_in[1];
    const int*   ety    = (const int*)  d_in[2];
    const float* emb    = (const float*)d_in[3];
    const float* comp1  = (const float*)d_in[4];
    const float* bases1 = (const float*)d_in[5];
    const float* root1  = (const float*)d_in[6];
    const float* bias1  = (const float*)d_in[7];
    const float* comp2  = (const float*)d_in[8];
    const float* bases2 = (const float*)d_in[9];
    const float* root2  = (const float*)d_in[10];
    const float* bias2  = (const float*)d_in[11];
    const int* src = ei;
    const int* dst = ei + NE;
    float* out = (float*)d_out;

    k_embed<<<(NN * 32 + 255) / 256, 256>>>(x, (const float4*)emb);

    k_zero_cnt  <<<(NR / 4 + 255) / 256, 256>>>();
    k_hist      <<<(NE + 255) / 256, 256>>>(dst, ety);
    k_seg_assign<<<(NR + 255) / 256, 256>>>();
    k_place     <<<(NE + 255) / 256, 256>>>(src, dst, ety);

    const int gemm_blocks = (NN + GBM - 1) / GBM;   // 391
    const int agg_blocks  = NN / 8;                 // 6250, exact

    k_wc       <<<(KTOT * DD / 4 + 255) / 256, 256>>>((const float4*)bases1, (const float4*)root1);
    k_aggregate<<<agg_blocks, 256>>>(0, comp1);
    k_gemm_tc  <<<gemm_blocks, 256>>>(bias1, nullptr, 1);

    k_wc       <<<(KTOT * DD / 4 + 255) / 256, 256>>>((const float4*)bases2, (const float4*)root2);
    k_aggregate<<<agg_blocks, 256>>>(1, comp2);
    k_gemm_tc  <<<gemm_blocks, 256>>>(bias2, out, 0);
}

// round 8
// speedup vs baseline: 1.3732x; 1.3732x over previous
#include <cuda_runtime.h>
#include <cuda_bf16.h>
#include <cstdint>
#include <cstddef>

#define NN 50000
#define NE 1600000
#define DD 128
#define RR 24
#define BB 8
#define KTOT (BB*DD + DD)     /* 1152 */
#define NR (NN*RR)            /* 1,200,000 */
#define WCF4 (KTOT*DD/4)      /* 36864 float4 in Wc */
#define WCBLK (WCF4/256)      /* 144 blocks convert Wc */

// ---------------- device scratch (no allocations allowed) ----------------
// NOTE: g_cnt/g_cursor are zero at process start (static init) and re-zeroed
// at the END of every kernel_launch call (inside the last gemm), so every
// call sees the same initial state and does identical work.
__device__ float g_h0[(size_t)NN * DD];
__device__ float g_h1[(size_t)NN * DD];
__device__ float g_A [(size_t)NN * KTOT];
__device__ float g_Wc[(size_t)KTOT * DD];
__device__ int   g_cnt[NR];
__device__ int   g_seg_start[NR];   // immutable segment starts
__device__ int   g_seg_off[NR];     // cursor; becomes segment END after k_place
__device__ int   g_sorted_src[NE];  // src ids grouped by (dst*R + type) segment
__device__ int   g_cursor;

// round-to-nearest tf32
__device__ __forceinline__ float tf32r(float x) {
    uint32_t u;
    asm("cvt.rna.tf32.f32 %0, %1;" : "=r"(u) : "f"(x));
    return __uint_as_float(u);
}

__device__ __forceinline__ void cp16(void* smem_ptr, const void* gptr, bool pred) {
    uint32_t s = (uint32_t)__cvta_generic_to_shared(smem_ptr);
    int sz = pred ? 16 : 0;
    asm volatile("cp.async.cg.shared.global [%0], [%1], 16, %2;\n"
                 :: "r"(s), "l"(gptr), "r"(sz));
}

// ---------------- setup kernels ----------------

__global__ void k_hist(const int* __restrict__ dst, const int* __restrict__ ety) {
    int e = blockIdx.x * blockDim.x + threadIdx.x;
    if (e < NE) atomicAdd(&g_cnt[dst[e] * RR + ety[e]], 1);
}

// Parallel segment-offset assignment: block-local exclusive scan of 256 counts,
// one global atomicAdd per block. Segment order is arbitrary; only intra-segment
// contiguity matters downstream.
__global__ __launch_bounds__(256) void k_seg_assign() {
    __shared__ int wtot[8];
    __shared__ int s_base;
    int i = blockIdx.x * 256 + threadIdx.x;
    int lane = threadIdx.x & 31, wid = threadIdx.x >> 5;
    int c = (i < NR) ? g_cnt[i] : 0;
    int incl = c;
    #pragma unroll
    for (int d = 1; d < 32; d <<= 1) {
        int t = __shfl_up_sync(0xffffffffu, incl, d);
        if (lane >= d) incl += t;
    }
    if (lane == 31) wtot[wid] = incl;
    __syncthreads();
    if (threadIdx.x == 0) {
        int s = 0;
        #pragma unroll
        for (int j = 0; j < 8; j++) { int t = wtot[j]; wtot[j] = s; s += t; }
        s_base = atomicAdd(&g_cursor, s);
    }
    __syncthreads();
    if (i < NR) {
        int off = s_base + wtot[wid] + incl - c;
        g_seg_start[i] = off;
        g_seg_off[i]   = off;
    }
}

// place edges into segments; ALSO does the embedding gather (both ranges are
// exactly NN*32 == NE == 1.6M threads).
__global__ void k_place_embed(const int* __restrict__ src, const int* __restrict__ dst,
                              const int* __restrict__ ety,
                              const int* __restrict__ x, const float4* __restrict__ emb) {
    int e = blockIdx.x * blockDim.x + threadIdx.x;
    if (e < NE) {
        int pos = atomicAdd(&g_seg_off[dst[e] * RR + ety[e]], 1);
        g_sorted_src[pos] = src[e];
    }
    if (e < NN * 32) {
        int n = e >> 5;
        int c = e & 31;
        ((float4*)g_h0)[e] = emb[(size_t)x[n] * 32 + c];
    }
}

// ---------------- aggregation: warp per node, flat edge loop ----------------
// Per warp: stage all (src | r<<16) of this node's edges into smem in one
// lane-parallel pass (full MLP on the srt loads), build per-node weight table
// w[r][b] = comp[r,b]/cnt_r, then unroll-4 gather loop with independent rows.
// First WCBLK blocks also convert bases++root -> g_Wc (tf32-rounded).
__global__ __launch_bounds__(256) void k_aggregate(int use_h1, const float* __restrict__ comp,
                                                   const float4* __restrict__ bases4,
                                                   const float4* __restrict__ root4) {
    const float4* __restrict__ h4 = (const float4*)(use_h1 ? g_h1 : g_h0);
    const int* __restrict__ srt = g_sorted_src;

    if (blockIdx.x < WCBLK) {
        int i = blockIdx.x * 256 + threadIdx.x;   // < WCF4 exactly
        float4 v = (i < BB * DD * DD / 4) ? bases4[i] : root4[i - BB * DD * DD / 4];
        v.x = tf32r(v.x); v.y = tf32r(v.y); v.z = tf32r(v.z); v.w = tf32r(v.w);
        ((float4*)g_Wc)[i] = v;
    }

    __shared__ float s_comp[RR * BB];
    __shared__ int   s_pk[8][128];
    __shared__ float s_w[8][RR * BB];
    for (int j = threadIdx.x; j < RR * BB; j += 256) s_comp[j] = comp[j];
    __syncthreads();

    const int lane = threadIdx.x & 31;
    const int wid  = threadIdx.x >> 5;
    const int n = (blockIdx.x * 256 + threadIdx.x) >> 5;   // 6250*8 = NN exactly

    int start_l = 0, cnt_l = 0;
    if (lane < RR) {
        start_l = g_seg_start[n * RR + lane];
        cnt_l   = g_seg_off[n * RR + lane] - start_l;   // END - start
    }
    // inclusive scan of cnt over lanes -> positions in the flat edge list
    int incl = cnt_l;
    #pragma unroll
    for (int d = 1; d < 32; d <<= 1) {
        int t = __shfl_up_sync(0xffffffffu, incl, d);
        if (lane >= d) incl += t;
    }
    const int pos_l = incl - cnt_l;
    const int total = __shfl_sync(0xffffffffu, incl, 31);

    float z[BB][4];
    #pragma unroll
    for (int b = 0; b < BB; b++)
        #pragma unroll
        for (int j = 0; j < 4; j++) z[b][j] = 0.f;

    if (total <= 128) {
        for (int j = 0; j < cnt_l; j++)
            s_pk[wid][pos_l + j] = __ldg(&srt[start_l + j]) | (lane << 16);
        if (lane < RR) {
            float invc = (cnt_l > 0) ? 1.0f / (float)cnt_l : 0.0f;
            #pragma unroll
            for (int b = 0; b < BB; b++)
                s_w[wid][lane * BB + b] = s_comp[lane * BB + b] * invc;
        }
        __syncwarp();

        int k = 0;
        for (; k + 3 < total; k += 4) {
            int p0 = s_pk[wid][k];
            int p1 = s_pk[wid][k + 1];
            int p2 = s_pk[wid][k + 2];
            int p3 = s_pk[wid][k + 3];
            float4 v0 = __ldg(&h4[(p0 & 0xFFFF) * 32 + lane]);
            float4 v1 = __ldg(&h4[(p1 & 0xFFFF) * 32 + lane]);
            float4 v2 = __ldg(&h4[(p2 & 0xFFFF) * 32 + lane]);
            float4 v3 = __ldg(&h4[(p3 & 0xFFFF) * 32 + lane]);
            const float* w0 = &s_w[wid][(p0 >> 16) * BB];
            const float* w1 = &s_w[wid][(p1 >> 16) * BB];
            const float* w2 = &s_w[wid][(p2 >> 16) * BB];
            const float* w3 = &s_w[wid][(p3 >> 16) * BB];
            #pragma unroll
            for (int b = 0; b < BB; b++) {
                float c0 = w0[b], c1 = w1[b], c2 = w2[b], c3 = w3[b];
                z[b][0] = fmaf(c0, v0.x, fmaf(c1, v1.x, fmaf(c2, v2.x, fmaf(c3, v3.x, z[b][0]))));
                z[b][1] = fmaf(c0, v0.y, fmaf(c1, v1.y, fmaf(c2, v2.y, fmaf(c3, v3.y, z[b][1]))));
                z[b][2] = fmaf(c0, v0.z, fmaf(c1, v1.z, fmaf(c2, v2.z, fmaf(c3, v3.z, z[b][2]))));
                z[b][3] = fmaf(c0, v0.w, fmaf(c1, v1.w, fmaf(c2, v2.w, fmaf(c3, v3.w, z[b][3]))));
            }
        }
        for (; k < total; k++) {
            int p0 = s_pk[wid][k];
            float4 v0 = __ldg(&h4[(p0 & 0xFFFF) * 32 + lane]);
            const float* w0 = &s_w[wid][(p0 >> 16) * BB];
            #pragma unroll
            for (int b = 0; b < BB; b++) {
                float c0 = w0[b];
                z[b][0] = fmaf(c0, v0.x, z[b][0]);
                z[b][1] = fmaf(c0, v0.y, z[b][1]);
                z[b][2] = fmaf(c0, v0.z, z[b][2]);
                z[b][3] = fmaf(c0, v0.w, z[b][3]);
            }
        }
    } else {
        // fallback: per-segment loop (extremely high-degree node)
        for (int r = 0; r < RR; r++) {
            int c  = __shfl_sync(0xffffffffu, cnt_l, r);
            if (c == 0) continue;
            int e0 = __shfl_sync(0xffffffffu, start_l, r);
            int e1 = e0 + c;
            float4 a0 = make_float4(0.f, 0.f, 0.f, 0.f);
            float4 a1 = a0, a2 = a0, a3 = a0;
            int e = e0;
            for (; e + 3 < e1; e += 4) {
                float4 v0 = __ldg(&h4[__ldg(&srt[e])     * 32 + lane]);
                float4 v1 = __ldg(&h4[__ldg(&srt[e + 1]) * 32 + lane]);
                float4 v2 = __ldg(&h4[__ldg(&srt[e + 2]) * 32 + lane]);
                float4 v3 = __ldg(&h4[__ldg(&srt[e + 3]) * 32 + lane]);
                a0.x += v0.x; a0.y += v0.y; a0.z += v0.z; a0.w += v0.w;
                a1.x += v1.x; a1.y += v1.y; a1.z += v1.z; a1.w += v1.w;
                a2.x += v2.x; a2.y += v2.y; a2.z += v2.z; a2.w += v2.w;
                a3.x += v3.x; a3.y += v3.y; a3.z += v3.z; a3.w += v3.w;
            }
            for (; e < e1; e++) {
                float4 v0 = __ldg(&h4[__ldg(&srt[e]) * 32 + lane]);
                a0.x += v0.x; a0.y += v0.y; a0.z += v0.z; a0.w += v0.w;
            }
            float inv = 1.0f / (float)c;
            float m0 = ((a0.x + a1.x) + (a2.x + a3.x)) * inv;
            float m1 = ((a0.y + a1.y) + (a2.y + a3.y)) * inv;
            float m2 = ((a0.z + a1.z) + (a2.z + a3.z)) * inv;
            float m3 = ((a0.w + a1.w) + (a2.w + a3.w)) * inv;
            #pragma unroll
            for (int b = 0; b < BB; b++) {
                float w = s_comp[r * BB + b];
                z[b][0] = fmaf(w, m0, z[b][0]);
                z[b][1] = fmaf(w, m1, z[b][1]);
                z[b][2] = fmaf(w, m2, z[b][2]);
                z[b][3] = fmaf(w, m3, z[b][3]);
            }
        }
    }

    float4* Arow = (float4*)&g_A[(size_t)n * KTOT];
    #pragma unroll
    for (int b = 0; b < BB; b++) {
        float4 v;
        v.x = tf32r(z[b][0]); v.y = tf32r(z[b][1]);
        v.z = tf32r(z[b][2]); v.w = tf32r(z[b][3]);
        Arow[b * 32 + lane] = v;
    }
    float4 hv = __ldg(&h4[n * 32 + lane]);
    hv.x = tf32r(hv.x); hv.y = tf32r(hv.y); hv.z = tf32r(hv.z); hv.w = tf32r(hv.w);
    Arow[BB * 32 + lane] = hv;
}

// ---------------- tf32 tensor-core GEMM ----------------
// out[N,128] = g_A[N,1152] @ g_Wc[1152,128] + bias (optional relu)
// BM=128, BN=128, BK=16, 256 threads (8 warps, warp tile 32x64), 2-stage cp.async.
// When zero_next!=0, also re-zeroes g_cnt/g_cursor for the NEXT call.
#define GBM 128
#define GBK 16
#define NITER (KTOT / GBK)   /* 72 */

__global__ __launch_bounds__(256, 2) void k_gemm_tc(const float* __restrict__ bias,
                                                    float* __restrict__ outp, int relu,
                                                    int zero_next) {
    if (zero_next) {
        for (int i = blockIdx.x * 256 + threadIdx.x; i < NR / 4; i += gridDim.x * 256)
            ((int4*)g_cnt)[i] = make_int4(0, 0, 0, 0);
        if (blockIdx.x == 0 && threadIdx.x == 0) g_cursor = 0;
    }

    __shared__ float As[2][GBM][20];
    __shared__ float Bs[2][GBK][136];

    const int tid  = threadIdx.x;
    const int wid  = tid >> 5;
    const int lane = tid & 31;
    const int g    = lane >> 2;
    const int q    = lane & 3;
    const int warp_m = (wid >> 1) * 32;
    const int warp_n = (wid & 1) * 64;
    const int row0 = blockIdx.x * GBM;

    float acc[2][8][4];
    #pragma unroll
    for (int mi = 0; mi < 2; mi++)
        #pragma unroll
        for (int nj = 0; nj < 8; nj++)
            #pragma unroll
            for (int k = 0; k < 4; k++) acc[mi][nj][k] = 0.f;

    #define LOAD_TILES(K0, BUF)                                                   \
    do {                                                                          \
        _Pragma("unroll")                                                         \
        for (int j = 0; j < 2; j++) {                                             \
            int idx = tid + j * 256;                                              \
            int ar = idx >> 2, ac = (idx & 3) * 4;                                \
            bool ok = (row0 + ar) < NN;                                           \
            const float* src = ok ? &g_A[(size_t)(row0 + ar) * KTOT + (K0) + ac]  \
                                  : &g_A[0];                                      \
            cp16(&As[BUF][ar][ac], src, ok);                                      \
        }                                                                         \
        _Pragma("unroll")                                                         \
        for (int j = 0; j < 2; j++) {                                             \
            int idx = tid + j * 256;                                              \
            int br = idx >> 5, bc = (idx & 31) * 4;                               \
            cp16(&Bs[BUF][br][bc], &g_Wc[(size_t)((K0) + br) * DD + bc], true);   \
        }                                                                         \
    } while (0)

    LOAD_TILES(0, 0);
    asm volatile("cp.async.commit_group;");

    for (int it = 0; it < NITER; it++) {
        const int cur = it & 1;
        const int nxt = cur ^ 1;
        if (it + 1 < NITER) LOAD_TILES((it + 1) * GBK, nxt);
        asm volatile("cp.async.commit_group;");
        asm volatile("cp.async.wait_group 1;");
        __syncthreads();

        #pragma unroll
        for (int s = 0; s < 2; s++) {
            const int kb = s * 8;
            uint32_t af[2][4];
            uint32_t bf[8][2];
            #pragma unroll
            for (int mi = 0; mi < 2; mi++) {
                int m = warp_m + mi * 16 + g;
                af[mi][0] = __float_as_uint(As[cur][m][kb + q]);
                af[mi][1] = __float_as_uint(As[cur][m + 8][kb + q]);
                af[mi][2] = __float_as_uint(As[cur][m][kb + q + 4]);
                af[mi][3] = __float_as_uint(As[cur][m + 8][kb + q + 4]);
            }
            #pragma unroll
            for (int nj = 0; nj < 8; nj++) {
                int n = warp_n + nj * 8 + g;
                bf[nj][0] = __float_as_uint(Bs[cur][kb + q][n]);
                bf[nj][1] = __float_as_uint(Bs[cur][kb + q + 4][n]);
            }
            #pragma unroll
            for (int mi = 0; mi < 2; mi++)
                #pragma unroll
                for (int nj = 0; nj < 8; nj++) {
                    asm volatile(
                        "mma.sync.aligned.m16n8k8.row.col.f32.tf32.tf32.f32 "
                        "{%0,%1,%2,%3}, {%4,%5,%6,%7}, {%8,%9}, {%0,%1,%2,%3};\n"
                        : "+f"(acc[mi][nj][0]), "+f"(acc[mi][nj][1]),
                          "+f"(acc[mi][nj][2]), "+f"(acc[mi][nj][3])
                        : "r"(af[mi][0]), "r"(af[mi][1]), "r"(af[mi][2]), "r"(af[mi][3]),
                          "r"(bf[nj][0]), "r"(bf[nj][1]));
                }
        }
        __syncthreads();
    }

    float* dstb = outp ? outp : g_h1;
    #pragma unroll
    for (int mi = 0; mi < 2; mi++) {
        #pragma unroll
        for (int nj = 0; nj < 8; nj++) {
            int c  = warp_n + nj * 8 + q * 2;
            float b0 = __ldg(&bias[c]);
            float b1 = __ldg(&bias[c + 1]);
            int ra = row0 + warp_m + mi * 16 + g;
            int rb = ra + 8;
            float2 v0, v1;
            v0.x = acc[mi][nj][0] + b0; v0.y = acc[mi][nj][1] + b1;
            v1.x = acc[mi][nj][2] + b0; v1.y = acc[mi][nj][3] + b1;
            if (relu) {
                v0.x = fmaxf(v0.x, 0.f); v0.y = fmaxf(v0.y, 0.f);
                v1.x = fmaxf(v1.x, 0.f); v1.y = fmaxf(v1.y, 0.f);
            }
            if (ra < NN) *(float2*)&dstb[(size_t)ra * DD + c] = v0;
            if (rb < NN) *(float2*)&dstb[(size_t)rb * DD + c] = v1;
        }
    }
}

// ---------------- host launch ----------------
extern "C" void kernel_launch(void* const* d_in, const int* in_sizes, int n_in,
                              void* d_out, int out_size) {
    const int*   x      = (const int*)  d_in[0];
    const int*   ei     = (const int*)  d_in[1];
    const int*   ety    = (const int*)  d_in[2];
    const float* emb    = (const float*)d_in[3];
    const float* comp1  = (const float*)d_in[4];
    const float* bases1 = (const float*)d_in[5];
    const float* root1  = (const float*)d_in[6];
    const float* bias1  = (const float*)d_in[7];
    const float* comp2  = (const float*)d_in[8];
    const float* bases2 = (const float*)d_in[9];
    const float* root2  = (const float*)d_in[10];
    const float* bias2  = (const float*)d_in[11];
    const int* src = ei;
    const int* dst = ei + NE;
    float* out = (float*)d_out;

    const int gemm_blocks = (NN + GBM - 1) / GBM;   // 391
    const int agg_blocks  = NN / 8;                 // 6250, exact

    // g_cnt/g_cursor are zero here: loader-init on call 1, gemm2-tail afterwards.
    k_hist       <<<(NE + 255) / 256, 256>>>(dst, ety);                 // #1
    k_seg_assign <<<(NR + 255) / 256, 256>>>();                         // #2
    k_place_embed<<<NE / 256, 256>>>(src, dst, ety, x, (const float4*)emb); // #3
    k_aggregate  <<<agg_blocks, 256>>>(0, comp1,                        // #4 (profiled)
                                       (const float4*)bases1, (const float4*)root1);
    k_gemm_tc    <<<gemm_blocks, 256>>>(bias1, nullptr, 1, 0);          // #5
    k_aggregate  <<<agg_blocks, 256>>>(1, comp2,                        // #6
                                       (const float4*)bases2, (const float4*)root2);
    k_gemm_tc    <<<gemm_blocks, 256>>>(bias2, out, 0, 1);              // #7
}